// round 12
// baseline (speedup 1.0000x reference)
#include <cuda_runtime.h>
#include <math_constants.h>

// WeightedChamferDistance: B=4, N=M=8192, D=3.
// out = mean_b( sum_n min_m d2 * w[b,n] ) + mean_b( sum_m min_n d2 )
//
// Exact NN: counting-sort both clouds into 512 x-bins; k_window scans, for
// each group of 512 rank-consecutive sorted queries, a STATIC candidate
// window = group's bin span +/- EXP bins, using the proven R3 engine
// (4 queries/thread, packed-pair fma.rn.f32x2 over shared tiles, 8 window
// splits -> 1024 uniform blocks, ~81M evals vs 537M brute force). pass2
// combines split mins, verifies the bin-edge pruning bound (exact under any
// intra-bin order), and the rare failures expand bins per-thread inline.

#define BATCH  4
#define NPTS   8192
#define NCLD   8                 // 0..3 = src batches, 4..7 = tgt batches
#define NBINS  512
#define XMIN   (-5.0f)
#define XW     (10.0f / (float)NBINS)
#define INVW   ((float)NBINS / 10.0f)
#define EXP    12                // margin bins (0.234 in x)
#define GQ     512               // queries per group
#define NGRP   (NPTS / GQ)       // 16 groups per cloud
#define WSPL   8                 // window splits per group
#define T1     128

__device__ int    g_cnt[NCLD * NBINS];
__device__ int    g_cur[NCLD * NBINS];
__device__ int    g_off[NCLD * (NBINS + 1)];
__device__ float4 g_od[NCLD * NPTS];       // bin-sorted, preprocessed (-2x,-2y,-2z,o2)
__device__ int    g_idx[NCLD * NPTS];      // original index of sorted entry
__device__ float  g_partial[NCLD * NPTS * WSPL];
__device__ float  g_contrib[NCLD * NPTS];

__global__ void k_init()
{
    const int i = blockIdx.x * blockDim.x + threadIdx.x;
    if (i < NCLD * NBINS) g_cnt[i] = 0;
}

__device__ __forceinline__ const float* cloud_pt(const float* src, const float* tgt,
                                                 int c, int i)
{
    return (c < BATCH) ? (src + ((size_t)c * NPTS + i) * 3)
                       : (tgt + ((size_t)(c - BATCH) * NPTS + i) * 3);
}

__device__ __forceinline__ int bin_of(float x)
{
    int b = (int)((x - XMIN) * INVW);
    return min(max(b, 0), NBINS - 1);
}

__global__ void k_hist(const float* __restrict__ src, const float* __restrict__ tgt)
{
    const int id = blockIdx.x * blockDim.x + threadIdx.x;
    const int c = id >> 13, i = id & (NPTS - 1);
    const float x = cloud_pt(src, tgt, c, i)[0];
    atomicAdd(&g_cnt[c * NBINS + bin_of(x)], 1);
}

__global__ __launch_bounds__(NBINS)
void k_prefix()              // one block per cloud
{
    __shared__ int sa[NBINS], sb[NBINS];
    const int t = threadIdx.x;
    const int c = blockIdx.x;
    sa[t] = g_cnt[c * NBINS + t];
    __syncthreads();
    int* in = sa;
    int* out = sb;
    #pragma unroll
    for (int s = 1; s < NBINS; s <<= 1) {
        out[t] = (t >= s) ? (in[t] + in[t - s]) : in[t];
        __syncthreads();
        int* tmp = in; in = out; out = tmp;
    }
    const int excl = (t == 0) ? 0 : in[t - 1];
    g_off[c * (NBINS + 1) + t] = excl;
    g_cur[c * NBINS + t] = excl;
    if (t == NBINS - 1) g_off[c * (NBINS + 1) + NBINS] = in[NBINS - 1];
}

__global__ void k_scatter(const float* __restrict__ src, const float* __restrict__ tgt)
{
    const int id = blockIdx.x * blockDim.x + threadIdx.x;
    const int c = id >> 13, i = id & (NPTS - 1);
    const float* p = cloud_pt(src, tgt, c, i);
    const float x = p[0], y = p[1], z = p[2];
    const int pos = atomicAdd(&g_cur[c * NBINS + bin_of(x)], 1);
    g_od[(size_t)c * NPTS + pos] =
        make_float4(-2.0f * x, -2.0f * y, -2.0f * z, x * x + y * y + z * z);
    g_idx[(size_t)c * NPTS + pos] = i;
}

// grid = NCLD * NGRP * WSPL = 1024 blocks of 128 threads
__global__ __launch_bounds__(T1, 12)
void k_window()
{
    __shared__ float s_tile[128 * 8];    // 256 candidates in pair layout

    const int bxc = blockIdx.x;
    const int s   = bxc & (WSPL - 1);
    const int g   = (bxc >> 3) & (NGRP - 1);
    const int c   = bxc >> 7;
    const int o   = c ^ BATCH;

    const float4* qd = g_od + (size_t)c * NPTS;
    const float4* od = g_od + (size_t)o * NPTS;
    const int* off = g_off + o * (NBINS + 1);

    // Static window: group's bin span +/- EXP (uniform across block)
    const float xf = -0.5f * qd[g * GQ].x;
    const float xl = -0.5f * qd[g * GQ + GQ - 1].x;
    const int blo = max(bin_of(xf) - EXP, 0);
    const int bhi = min(bin_of(xl) + EXP, NBINS - 1);
    const int wlo = off[blo], whi = off[bhi + 1];
    const int chunk = (whi - wlo + WSPL - 1) / WSPL;
    const int cstart = wlo + s * chunk;
    const int cend = min(cstart + chunk, whi);

    // Load this thread's four queries (sorted order); duplicate coords
    const int pos0 = g * GQ + threadIdx.x;
    unsigned long long cx[4], cy[4], cz[4];
    #pragma unroll
    for (int k = 0; k < 4; ++k) {
        const float4 v = qd[pos0 + k * T1];
        const float qx = -0.5f * v.x, qy = -0.5f * v.y, qz = -0.5f * v.z;
        asm("mov.b64 %0,{%1,%1};" : "=l"(cx[k]) : "f"(qx));
        asm("mov.b64 %0,{%1,%1};" : "=l"(cy[k]) : "f"(qy));
        asm("mov.b64 %0,{%1,%1};" : "=l"(cz[k]) : "f"(qz));
    }

    unsigned sbase;
    asm("{ .reg .u64 t; cvta.to.shared.u64 t, %1; cvt.u32.u64 %0, t; }"
        : "=r"(sbase) : "l"(s_tile));

    float m0[4], m1[4];
    #pragma unroll
    for (int k = 0; k < 4; ++k) { m0[k] = CUDART_INF_F; m1[k] = CUDART_INF_F; }

    for (int base = cstart; base < cend; base += 256) {
        const int n = min(cend - base, 256);
        __syncthreads();
        #pragma unroll
        for (int t = 0; t < 2; ++t) {
            const int j = t * T1 + threadIdx.x;
            const float4 v = (j < n) ? __ldg(&od[base + j])
                                     : make_float4(0.0f, 0.0f, 0.0f, CUDART_INF_F);
            float* bp = s_tile + (j >> 1) * 8 + (j & 1);
            bp[0] = v.x; bp[2] = v.y; bp[4] = v.z; bp[6] = v.w;
        }
        __syncthreads();
        const int npairs = (n + 1) >> 1;
        #pragma unroll 4
        for (int kk = 0; kk < npairs; ++kk) {
            const unsigned a = sbase + kk * 32u;
            unsigned long long txp, typ, tzp, t2p;
            asm("ld.shared.v2.u64 {%0,%1},[%2];" : "=l"(txp), "=l"(typ) : "r"(a));
            asm("ld.shared.v2.u64 {%0,%1},[%2];" : "=l"(tzp), "=l"(t2p) : "r"(a + 16u));
            unsigned long long acc[4];
            #pragma unroll
            for (int k = 0; k < 4; ++k)
                asm("fma.rn.f32x2 %0,%1,%2,%3;" : "=l"(acc[k]) : "l"(cx[k]), "l"(txp), "l"(t2p));
            #pragma unroll
            for (int k = 0; k < 4; ++k)
                asm("fma.rn.f32x2 %0,%1,%2,%3;" : "=l"(acc[k]) : "l"(cy[k]), "l"(typ), "l"(acc[k]));
            #pragma unroll
            for (int k = 0; k < 4; ++k)
                asm("fma.rn.f32x2 %0,%1,%2,%3;" : "=l"(acc[k]) : "l"(cz[k]), "l"(tzp), "l"(acc[k]));
            #pragma unroll
            for (int k = 0; k < 4; ++k) {
                float lo, hi;
                asm("mov.b64 {%0,%1},%2;" : "=f"(lo), "=f"(hi) : "l"(acc[k]));
                m0[k] = fminf(m0[k], lo);
                m1[k] = fminf(m1[k], hi);
            }
        }
    }

    #pragma unroll
    for (int k = 0; k < 4; ++k)
        g_partial[(size_t)((size_t)c * NPTS + pos0 + k * T1) * WSPL + s] =
            fminf(m0[k], m1[k]);
}

// Combine splits, verify pruning bound, rare inline bin expansion, weight.
__global__ __launch_bounds__(256)
void k_pass2(const float* __restrict__ w)
{
    const int q = blockIdx.x * 256 + threadIdx.x;   // 0..65535
    const int c = q >> 13, pos = q & (NPTS - 1);
    const int o = c ^ BATCH;
    const int g = pos / GQ;

    const float4 qv = g_od[(size_t)c * NPTS + pos];
    const float qx = -0.5f * qv.x, qy = -0.5f * qv.y, qz = -0.5f * qv.z;
    const float p2 = qv.w;

    const float* pp = g_partial + (size_t)q * WSPL;
    float m = CUDART_INF_F;
    #pragma unroll
    for (int i = 0; i < WSPL; ++i) m = fminf(m, pp[i]);

    // Recompute this group's window (matches k_window)
    const float4* qd = g_od + (size_t)c * NPTS;
    const float4* od = g_od + (size_t)o * NPTS;
    const int* off = g_off + o * (NBINS + 1);
    const float xf = -0.5f * qd[g * GQ].x;
    const float xl = -0.5f * qd[g * GQ + GQ - 1].x;
    const int blo = max(bin_of(xf) - EXP, 0);
    const int bhi = min(bin_of(xl) + EXP, NBINS - 1);

    // Rare fallback: expand bins while the edge bound cannot prune
    for (int bb = blo - 1; bb >= 0; --bb) {
        const float dx = qx - (XMIN + (float)(bb + 1) * XW);
        if (dx > 0.0f && dx * dx > m + p2) break;
        for (int j = off[bb]; j < off[bb + 1]; ++j) {
            const float4 v = __ldg(&od[j]);
            float dd = fmaf(qx, v.x, v.w);
            dd = fmaf(qy, v.y, dd);
            dd = fmaf(qz, v.z, dd);
            m = fminf(m, dd);
        }
    }
    for (int bb = bhi + 1; bb < NBINS; ++bb) {
        const float dx = (XMIN + (float)bb * XW) - qx;
        if (dx > 0.0f && dx * dx > m + p2) break;
        for (int j = off[bb]; j < off[bb + 1]; ++j) {
            const float4 v = __ldg(&od[j]);
            float dd = fmaf(qx, v.x, v.w);
            dd = fmaf(qy, v.y, dd);
            dd = fmaf(qz, v.z, dd);
            m = fminf(m, dd);
        }
    }

    const int orig = g_idx[(size_t)c * NPTS + pos];
    const float qw = (c < BATCH) ? w[(size_t)c * NPTS + orig] : 1.0f;
    g_contrib[(size_t)c * NPTS + orig] = (m + p2) * qw;
}

__global__ __launch_bounds__(1024)
void k_sum(float* __restrict__ out)
{
    __shared__ float s_red[1024];
    float acc = 0.0f;
    #pragma unroll
    for (int i = 0; i < (NCLD * NPTS) / 1024; ++i)
        acc += g_contrib[(size_t)i * 1024 + threadIdx.x];
    s_red[threadIdx.x] = acc;
    __syncthreads();
    #pragma unroll
    for (int s = 512; s > 0; s >>= 1) {
        if (threadIdx.x < s) s_red[threadIdx.x] += s_red[threadIdx.x + s];
        __syncthreads();
    }
    if (threadIdx.x == 0) out[0] = s_red[0] * (1.0f / (float)BATCH);
}

extern "C" void kernel_launch(void* const* d_in, const int* in_sizes, int n_in,
                              void* d_out, int out_size)
{
    const float* src = (const float*)d_in[0];   // [B, N, 3]
    const float* tgt = (const float*)d_in[1];   // [B, M, 3]
    const float* w   = (const float*)d_in[2];   // [B, N]
    float* out = (float*)d_out;

    k_init<<<(NCLD * NBINS + 255) / 256, 256>>>();
    k_hist<<<NCLD * NPTS / 256, 256>>>(src, tgt);
    k_prefix<<<NCLD, NBINS>>>();
    k_scatter<<<NCLD * NPTS / 256, 256>>>(src, tgt);
    k_window<<<NCLD * NGRP * WSPL, T1>>>();
    k_pass2<<<NCLD * NPTS / 256, 256>>>(w);
    k_sum<<<1, 1024>>>(out);
}

// round 13
// speedup vs baseline: 6.5453x; 6.5453x over previous
#include <cuda_runtime.h>
#include <math_constants.h>

// WeightedChamferDistance: B=4, N=M=8192, D=3.
// out = mean_b( sum_n min_m d2 * w[b,n] ) + mean_b( sum_m min_n d2 )
//
// R4 champion engine (packed-pair fma.rn.f32x2, 4 points/thread, 512-other
// shared tiles with register prefetch) wrapped in a persistent work-stealing
// loop: 1184 blocks (148 SMs x 8 resident) pull 2048 items off a global
// counter, removing the ~7% block-slot imbalance of the static 2048-block
// grid. Item->output mapping is fixed, so assignment order doesn't affect
// results (deterministic).
// Pass2: min over 16 split-partials, weight fwd direction, block reduce.
// Pass3: final sum of 256 block sums, /BATCH.

#define BATCH   4
#define NPTS    8192
#define TILE    512             // others per item (8 KB tile)
#define SPLITS  16              // NPTS / TILE
#define T1      128             // threads (4 points each)
#define PPB     512             // points per item
#define NITEMS  (2 * BATCH * (NPTS / PPB) * SPLITS)   // 2048
#define NBLOCKS (148 * 8)       // persistent grid, all resident

__device__ float g_partial[2 * BATCH * NPTS * SPLITS];  // 4 MB
__device__ float g_sums[256];
__device__ unsigned int g_ctr;

__global__ void init_kernel() { g_ctr = 0u; }

__global__ __launch_bounds__(T1, 8)
void chamfer_pass1(const float* __restrict__ src,
                   const float* __restrict__ tgt)
{
    // Tile layout per pair k (8 floats = 32 B):
    //  [0]=-2x0 [1]=-2x1 [2]=-2y0 [3]=-2y1 [4]=-2z0 [5]=-2z1 [6]=o2_0 [7]=o2_1
    __shared__ float s_tile[TILE * 4 + 8];   // +8 floats: prefetch overread pad
    __shared__ unsigned int s_item;

    unsigned sbase;
    asm("{ .reg .u64 t; cvta.to.shared.u64 t, %1; cvt.u32.u64 %0, t; }"
        : "=r"(sbase) : "l"(s_tile));

    for (;;) {
        __syncthreads();                       // all done with s_tile/s_item
        if (threadIdx.x == 0) s_item = atomicAdd(&g_ctr, 1u);
        __syncthreads();
        const unsigned item = s_item;
        if (item >= NITEMS) break;

        const int split = item & (SPLITS - 1);
        const int g     = item >> 4;                     // 0..127 point-group id
        const bool bwd  = g >= (BATCH * (NPTS / PPB));   // >= 64
        const int lg    = g & 63;
        const int b     = lg >> 4;
        const int pg    = lg & 15;

        const float* pts = bwd ? tgt : src;
        const float* oth = bwd ? src : tgt;

        const int pid0 = pg * PPB + threadIdx.x;         // +0,+128,+256,+384

        // Load this thread's four points; duplicate into packed operands
        unsigned long long cx[4], cy[4], cz[4];
        float p2[4];
        #pragma unroll
        for (int k = 0; k < 4; ++k) {
            const float* p = pts + ((size_t)b * NPTS + pid0 + k * T1) * 3;
            const float x = p[0], y = p[1], z = p[2];
            p2[k] = x * x + y * y + z * z;
            asm("mov.b64 %0,{%1,%1};" : "=l"(cx[k]) : "f"(x));
            asm("mov.b64 %0,{%1,%1};" : "=l"(cy[k]) : "f"(y));
            asm("mov.b64 %0,{%1,%1};" : "=l"(cz[k]) : "f"(z));
        }

        // Cooperative tile load + preprocess for this chunk
        const float* obase = oth + ((size_t)b * NPTS + split * TILE) * 3;
        #pragma unroll
        for (int it = 0; it < TILE / T1; ++it) {
            const int idx = it * T1 + threadIdx.x;
            const float* o = obase + (size_t)idx * 3;
            const float ox = o[0], oy = o[1], oz = o[2];
            const float o2 = ox * ox + oy * oy + oz * oz;
            float* bp = s_tile + (idx >> 1) * 8 + (idx & 1);
            bp[0] = -2.0f * ox;
            bp[2] = -2.0f * oy;
            bp[4] = -2.0f * oz;
            bp[6] = o2;
        }
        __syncthreads();

        float m0[4], m1[4];
        #pragma unroll
        for (int k = 0; k < 4; ++k) { m0[k] = CUDART_INF_F; m1[k] = CUDART_INF_F; }

        // Prefetch iter 0's operands (R4's proven ILP win)
        unsigned long long txp, typ, tzp, t2p;
        asm("ld.shared.v2.u64 {%0,%1},[%2];" : "=l"(txp), "=l"(typ) : "r"(sbase));
        asm("ld.shared.v2.u64 {%0,%1},[%2];" : "=l"(tzp), "=l"(t2p) : "r"(sbase + 16u));

        #pragma unroll 8
        for (int kk = 0; kk < TILE / 2; ++kk) {
            const unsigned a = sbase + kk * 32u + 32u;
            unsigned long long ntx, nty, ntz, nt2;
            asm("ld.shared.v2.u64 {%0,%1},[%2];" : "=l"(ntx), "=l"(nty) : "r"(a));
            asm("ld.shared.v2.u64 {%0,%1},[%2];" : "=l"(ntz), "=l"(nt2) : "r"(a + 16u));
            #pragma unroll
            for (int k = 0; k < 4; ++k) {
                unsigned long long acc;
                asm("fma.rn.f32x2 %0,%1,%2,%3;" : "=l"(acc) : "l"(cx[k]), "l"(txp), "l"(t2p));
                asm("fma.rn.f32x2 %0,%1,%2,%3;" : "=l"(acc) : "l"(cy[k]), "l"(typ), "l"(acc));
                asm("fma.rn.f32x2 %0,%1,%2,%3;" : "=l"(acc) : "l"(cz[k]), "l"(tzp), "l"(acc));
                float lo, hi;
                asm("mov.b64 {%0,%1},%2;" : "=f"(lo), "=f"(hi) : "l"(acc));
                m0[k] = fminf(m0[k], lo);
                m1[k] = fminf(m1[k], hi);
            }
            txp = ntx; typ = nty; tzp = ntz; t2p = nt2;
        }

        const int base = ((int)bwd * BATCH + b) * NPTS;
        #pragma unroll
        for (int k = 0; k < 4; ++k) {
            g_partial[(size_t)(base + pid0 + k * T1) * SPLITS + split] =
                p2[k] + fminf(m0[k], m1[k]);
        }
    }
}

__global__ __launch_bounds__(256)
void chamfer_pass2(const float* __restrict__ w)
{
    __shared__ float s_red[256];

    const int q = blockIdx.x * 256 + threadIdx.x;   // 0 .. 65535
    const int bwd = q >> 15;                        // 0 = fwd (weighted)
    const int r   = q & 32767;
    const int b   = r >> 13;
    const int pid = r & (NPTS - 1);

    const float4* pp = (const float4*)(g_partial + (size_t)q * SPLITS);
    float m = CUDART_INF_F;
    #pragma unroll
    for (int i = 0; i < SPLITS / 4; ++i) {
        const float4 v = pp[i];
        m = fminf(m, fminf(fminf(v.x, v.y), fminf(v.z, v.w)));
    }
    if (!bwd) m *= w[(size_t)b * NPTS + pid];

    s_red[threadIdx.x] = m;
    __syncthreads();
    #pragma unroll
    for (int s = 128; s > 0; s >>= 1) {
        if (threadIdx.x < s) s_red[threadIdx.x] += s_red[threadIdx.x + s];
        __syncthreads();
    }
    if (threadIdx.x == 0) g_sums[blockIdx.x] = s_red[0];
}

__global__ void chamfer_pass3(float* __restrict__ out)
{
    __shared__ float s_red[256];
    s_red[threadIdx.x] = g_sums[threadIdx.x];
    __syncthreads();
    #pragma unroll
    for (int s = 128; s > 0; s >>= 1) {
        if (threadIdx.x < s) s_red[threadIdx.x] += s_red[threadIdx.x + s];
        __syncthreads();
    }
    if (threadIdx.x == 0) out[0] = s_red[0] * (1.0f / (float)BATCH);
}

extern "C" void kernel_launch(void* const* d_in, const int* in_sizes, int n_in,
                              void* d_out, int out_size)
{
    const float* src = (const float*)d_in[0];   // [B, N, 3]
    const float* tgt = (const float*)d_in[1];   // [B, M, 3]
    const float* w   = (const float*)d_in[2];   // [B, N]
    float* out = (float*)d_out;

    init_kernel<<<1, 1>>>();
    chamfer_pass1<<<NBLOCKS, T1>>>(src, tgt);
    chamfer_pass2<<<256, 256>>>(w);
    chamfer_pass3<<<1, 256>>>(out);
}

// round 14
// speedup vs baseline: 6.6726x; 1.0194x over previous
#include <cuda_runtime.h>
#include <math_constants.h>

// WeightedChamferDistance: B=4, N=M=8192, D=3.
// out = mean_b( sum_n min_m d2 * w[b,n] ) + mean_b( sum_m min_n d2 )
//
// Pass1: 2048 blocks; each = 512 points (4/thread, 128 threads) x one
//        512-other chunk. Others in shared as packed pairs
//        (-2x,-2y,-2z,|o|^2); fma.rn.f32x2 = 2 others/instr. Untried config
//        cell: R4's grid/tile shape but WITHOUT explicit prefetch -> ~40 regs
//        -> launch_bounds(128,12) gives 12 resident blocks (48 warps/SM),
//        highest warp count at R4-level per-item overhead.
// Pass2: min over 16 split-partials, weight fwd direction, block reduce.
// Pass3: final sum of 256 block sums, /BATCH.

#define BATCH   4
#define NPTS    8192
#define TILE    512             // others per chunk (8 KB tile)
#define SPLITS  16              // NPTS / TILE
#define T1      128             // pass1 threads (4 points each)
#define PPB     512             // points per block

__device__ float g_partial[2 * BATCH * NPTS * SPLITS];  // 4 MB
__device__ float g_sums[256];

__global__ __launch_bounds__(T1, 12)
void chamfer_pass1(const float* __restrict__ src,
                   const float* __restrict__ tgt)
{
    // Tile layout per pair k (8 floats = 32 B):
    //  [0]=-2x0 [1]=-2x1 [2]=-2y0 [3]=-2y1 [4]=-2z0 [5]=-2z1 [6]=o2_0 [7]=o2_1
    __shared__ float s_tile[TILE * 4];

    const int bx    = blockIdx.x;
    const int split = bx & (SPLITS - 1);
    const int g     = bx >> 4;                       // 0..127 point-group id
    const bool bwd  = g >= (BATCH * (NPTS / PPB));   // >= 64
    const int lg    = g & 63;
    const int b     = lg >> 4;
    const int pg    = lg & 15;

    const float* pts = bwd ? tgt : src;
    const float* oth = bwd ? src : tgt;

    const int pid0 = pg * PPB + threadIdx.x;         // +0,+128,+256,+384

    // Load this thread's four points; duplicate coords into packed operands
    unsigned long long cx[4], cy[4], cz[4];
    float p2[4];
    #pragma unroll
    for (int k = 0; k < 4; ++k) {
        const float* p = pts + ((size_t)b * NPTS + pid0 + k * T1) * 3;
        const float x = p[0], y = p[1], z = p[2];
        p2[k] = x * x + y * y + z * z;
        asm("mov.b64 %0,{%1,%1};" : "=l"(cx[k]) : "f"(x));
        asm("mov.b64 %0,{%1,%1};" : "=l"(cy[k]) : "f"(y));
        asm("mov.b64 %0,{%1,%1};" : "=l"(cz[k]) : "f"(z));
    }

    unsigned sbase;
    asm("{ .reg .u64 t; cvta.to.shared.u64 t, %1; cvt.u32.u64 %0, t; }"
        : "=r"(sbase) : "l"(s_tile));

    // Cooperative tile load + preprocess for this chunk
    const float* obase = oth + ((size_t)b * NPTS + split * TILE) * 3;
    #pragma unroll
    for (int it = 0; it < TILE / T1; ++it) {
        const int idx = it * T1 + threadIdx.x;
        const float* o = obase + (size_t)idx * 3;
        const float ox = o[0], oy = o[1], oz = o[2];
        const float o2 = ox * ox + oy * oy + oz * oz;
        float* bp = s_tile + (idx >> 1) * 8 + (idx & 1);
        bp[0] = -2.0f * ox;
        bp[2] = -2.0f * oy;
        bp[4] = -2.0f * oz;
        bp[6] = o2;
    }
    __syncthreads();

    float m0[4], m1[4];
    #pragma unroll
    for (int k = 0; k < 4; ++k) { m0[k] = CUDART_INF_F; m1[k] = CUDART_INF_F; }

    // Scan: TILE/2 packed pairs; 4 points share each pair of LDS.128
    #pragma unroll 8
    for (int kk = 0; kk < TILE / 2; ++kk) {
        const unsigned a = sbase + kk * 32u;
        unsigned long long txp, typ, tzp, t2p;
        asm("ld.shared.v2.u64 {%0,%1},[%2];" : "=l"(txp), "=l"(typ) : "r"(a));
        asm("ld.shared.v2.u64 {%0,%1},[%2];" : "=l"(tzp), "=l"(t2p) : "r"(a + 16u));
        unsigned long long acc[4];
        #pragma unroll
        for (int k = 0; k < 4; ++k)
            asm("fma.rn.f32x2 %0,%1,%2,%3;" : "=l"(acc[k]) : "l"(cx[k]), "l"(txp), "l"(t2p));
        #pragma unroll
        for (int k = 0; k < 4; ++k)
            asm("fma.rn.f32x2 %0,%1,%2,%3;" : "=l"(acc[k]) : "l"(cy[k]), "l"(typ), "l"(acc[k]));
        #pragma unroll
        for (int k = 0; k < 4; ++k)
            asm("fma.rn.f32x2 %0,%1,%2,%3;" : "=l"(acc[k]) : "l"(cz[k]), "l"(tzp), "l"(acc[k]));
        #pragma unroll
        for (int k = 0; k < 4; ++k) {
            float lo, hi;
            asm("mov.b64 {%0,%1},%2;" : "=f"(lo), "=f"(hi) : "l"(acc[k]));
            m0[k] = fminf(m0[k], lo);
            m1[k] = fminf(m1[k], hi);
        }
    }

    const int base = ((int)bwd * BATCH + b) * NPTS;
    #pragma unroll
    for (int k = 0; k < 4; ++k) {
        g_partial[(size_t)(base + pid0 + k * T1) * SPLITS + split] =
            p2[k] + fminf(m0[k], m1[k]);
    }
}

__global__ __launch_bounds__(256)
void chamfer_pass2(const float* __restrict__ w)
{
    __shared__ float s_red[256];

    const int q = blockIdx.x * 256 + threadIdx.x;   // 0 .. 65535
    const int bwd = q >> 15;                        // 0 = fwd (weighted)
    const int r   = q & 32767;
    const int b   = r >> 13;
    const int pid = r & (NPTS - 1);

    const float4* pp = (const float4*)(g_partial + (size_t)q * SPLITS);
    float m = CUDART_INF_F;
    #pragma unroll
    for (int i = 0; i < SPLITS / 4; ++i) {
        const float4 v = pp[i];
        m = fminf(m, fminf(fminf(v.x, v.y), fminf(v.z, v.w)));
    }
    if (!bwd) m *= w[(size_t)b * NPTS + pid];

    s_red[threadIdx.x] = m;
    __syncthreads();
    #pragma unroll
    for (int s = 128; s > 0; s >>= 1) {
        if (threadIdx.x < s) s_red[threadIdx.x] += s_red[threadIdx.x + s];
        __syncthreads();
    }
    if (threadIdx.x == 0) g_sums[blockIdx.x] = s_red[0];
}

__global__ void chamfer_pass3(float* __restrict__ out)
{
    __shared__ float s_red[256];
    s_red[threadIdx.x] = g_sums[threadIdx.x];
    __syncthreads();
    #pragma unroll
    for (int s = 128; s > 0; s >>= 1) {
        if (threadIdx.x < s) s_red[threadIdx.x] += s_red[threadIdx.x + s];
        __syncthreads();
    }
    if (threadIdx.x == 0) out[0] = s_red[0] * (1.0f / (float)BATCH);
}

extern "C" void kernel_launch(void* const* d_in, const int* in_sizes, int n_in,
                              void* d_out, int out_size)
{
    const float* src = (const float*)d_in[0];   // [B, N, 3]
    const float* tgt = (const float*)d_in[1];   // [B, M, 3]
    const float* w   = (const float*)d_in[2];   // [B, N]
    float* out = (float*)d_out;

    // 2 dirs * 4 batches * 16 point-groups * 16 splits = 2048 blocks
    chamfer_pass1<<<2 * BATCH * (NPTS / PPB) * SPLITS, T1>>>(src, tgt);
    chamfer_pass2<<<256, 256>>>(w);
    chamfer_pass3<<<1, 256>>>(out);
}

// round 15
// speedup vs baseline: 6.9599x; 1.0430x over previous
#include <cuda_runtime.h>
#include <math_constants.h>

// WeightedChamferDistance: B=4, N=M=8192, D=3.
// out = mean_b( sum_n min_m d2 * w[b,n] ) + mean_b( sum_m min_n d2 )
//
// Session champion (R4 configuration, 77.2 us measured):
// Pass1: 2048 blocks; each block = 512 points (4/thread, 128 threads) x one
//        512-other chunk. Others preprocessed in shared as packed pairs
//        (-2x,-2y,-2z,|o|^2); fma.rn.f32x2 = 2 others/instr (1.5 instr/eval);
//        next iteration's LDS.128 pair is prefetched into registers so
//        shared-mem latency never sits on the FMA chain.
// Pass2: min over 16 split-partials, weight fwd direction, block reduce.
// Pass3: final sum of 256 block sums, /BATCH.
//
// Session findings (R3-R14): issue efficiency is pinned at 54-58% for this
// inner loop across occupancy 14-63%, regs 40-110, tile 256-1024, static/
// persistent grids; packed-min (min.f32x2) does not exist in PTX; sorted/
// pruned NN variants (6.6-10x fewer evals) lose on divergence + gather
// inefficiency. This exact configuration was the empirical minimum.

#define BATCH   4
#define NPTS    8192
#define TILE    512             // others per chunk (8 KB tile)
#define SPLITS  16              // NPTS / TILE
#define T1      128             // pass1 threads (4 points each)
#define PPB     512             // points per block

__device__ float g_partial[2 * BATCH * NPTS * SPLITS];  // 4 MB
__device__ float g_sums[256];

__global__ __launch_bounds__(T1, 8)
void chamfer_pass1(const float* __restrict__ src,
                   const float* __restrict__ tgt)
{
    // Tile layout per pair k (8 floats = 32 B):
    //  [0]=-2x0 [1]=-2x1 [2]=-2y0 [3]=-2y1 [4]=-2z0 [5]=-2z1 [6]=o2_0 [7]=o2_1
    __shared__ float s_tile[TILE * 4 + 8];   // +8 floats: prefetch overread pad

    const int bx    = blockIdx.x;
    const int split = bx & (SPLITS - 1);
    const int g     = bx >> 4;                       // 0..127 point-group id
    const bool bwd  = g >= (BATCH * (NPTS / PPB));   // >= 64
    const int lg    = g & 63;
    const int b     = lg >> 4;
    const int pg    = lg & 15;

    const float* pts = bwd ? tgt : src;
    const float* oth = bwd ? src : tgt;

    const int pid0 = pg * PPB + threadIdx.x;         // +0,+128,+256,+384

    // Load this thread's four points; duplicate coords into packed operands
    unsigned long long cx[4], cy[4], cz[4];
    float p2[4];
    #pragma unroll
    for (int k = 0; k < 4; ++k) {
        const float* p = pts + ((size_t)b * NPTS + pid0 + k * T1) * 3;
        const float x = p[0], y = p[1], z = p[2];
        p2[k] = x * x + y * y + z * z;
        asm("mov.b64 %0,{%1,%1};" : "=l"(cx[k]) : "f"(x));
        asm("mov.b64 %0,{%1,%1};" : "=l"(cy[k]) : "f"(y));
        asm("mov.b64 %0,{%1,%1};" : "=l"(cz[k]) : "f"(z));
    }

    unsigned sbase;
    asm("{ .reg .u64 t; cvta.to.shared.u64 t, %1; cvt.u32.u64 %0, t; }"
        : "=r"(sbase) : "l"(s_tile));

    // Cooperative tile load + preprocess for this chunk
    const float* obase = oth + ((size_t)b * NPTS + split * TILE) * 3;
    #pragma unroll
    for (int it = 0; it < TILE / T1; ++it) {
        const int idx = it * T1 + threadIdx.x;
        const float* o = obase + (size_t)idx * 3;
        const float ox = o[0], oy = o[1], oz = o[2];
        const float o2 = ox * ox + oy * oy + oz * oz;
        float* bp = s_tile + (idx >> 1) * 8 + (idx & 1);
        bp[0] = -2.0f * ox;
        bp[2] = -2.0f * oy;
        bp[4] = -2.0f * oz;
        bp[6] = o2;
    }
    __syncthreads();

    float m0[4], m1[4];
    #pragma unroll
    for (int k = 0; k < 4; ++k) { m0[k] = CUDART_INF_F; m1[k] = CUDART_INF_F; }

    // Scan with register prefetch: iter kk computes on (txp..t2p) while
    // (ntx..nt2) for kk+1 is in flight. Last iter overreads into the pad.
    unsigned long long txp, typ, tzp, t2p;
    asm("ld.shared.v2.u64 {%0,%1},[%2];" : "=l"(txp), "=l"(typ) : "r"(sbase));
    asm("ld.shared.v2.u64 {%0,%1},[%2];" : "=l"(tzp), "=l"(t2p) : "r"(sbase + 16u));

    #pragma unroll 8
    for (int kk = 0; kk < TILE / 2; ++kk) {
        const unsigned a = sbase + kk * 32u + 32u;
        unsigned long long ntx, nty, ntz, nt2;
        asm("ld.shared.v2.u64 {%0,%1},[%2];" : "=l"(ntx), "=l"(nty) : "r"(a));
        asm("ld.shared.v2.u64 {%0,%1},[%2];" : "=l"(ntz), "=l"(nt2) : "r"(a + 16u));
        #pragma unroll
        for (int k = 0; k < 4; ++k) {
            unsigned long long acc;
            asm("fma.rn.f32x2 %0,%1,%2,%3;" : "=l"(acc) : "l"(cx[k]), "l"(txp), "l"(t2p));
            asm("fma.rn.f32x2 %0,%1,%2,%3;" : "=l"(acc) : "l"(cy[k]), "l"(typ), "l"(acc));
            asm("fma.rn.f32x2 %0,%1,%2,%3;" : "=l"(acc) : "l"(cz[k]), "l"(tzp), "l"(acc));
            float lo, hi;
            asm("mov.b64 {%0,%1},%2;" : "=f"(lo), "=f"(hi) : "l"(acc));
            m0[k] = fminf(m0[k], lo);
            m1[k] = fminf(m1[k], hi);
        }
        txp = ntx; typ = nty; tzp = ntz; t2p = nt2;
    }

    const int base = ((int)bwd * BATCH + b) * NPTS;
    #pragma unroll
    for (int k = 0; k < 4; ++k) {
        g_partial[(size_t)(base + pid0 + k * T1) * SPLITS + split] =
            p2[k] + fminf(m0[k], m1[k]);
    }
}

__global__ __launch_bounds__(256)
void chamfer_pass2(const float* __restrict__ w)
{
    __shared__ float s_red[256];

    const int q = blockIdx.x * 256 + threadIdx.x;   // 0 .. 65535
    const int bwd = q >> 15;                        // 0 = fwd (weighted)
    const int r   = q & 32767;
    const int b   = r >> 13;
    const int pid = r & (NPTS - 1);

    const float4* pp = (const float4*)(g_partial + (size_t)q * SPLITS);
    float m = CUDART_INF_F;
    #pragma unroll
    for (int i = 0; i < SPLITS / 4; ++i) {
        const float4 v = pp[i];
        m = fminf(m, fminf(fminf(v.x, v.y), fminf(v.z, v.w)));
    }
    if (!bwd) m *= w[(size_t)b * NPTS + pid];

    s_red[threadIdx.x] = m;
    __syncthreads();
    #pragma unroll
    for (int s = 128; s > 0; s >>= 1) {
        if (threadIdx.x < s) s_red[threadIdx.x] += s_red[threadIdx.x + s];
        __syncthreads();
    }
    if (threadIdx.x == 0) g_sums[blockIdx.x] = s_red[0];
}

__global__ void chamfer_pass3(float* __restrict__ out)
{
    __shared__ float s_red[256];
    s_red[threadIdx.x] = g_sums[threadIdx.x];
    __syncthreads();
    #pragma unroll
    for (int s = 128; s > 0; s >>= 1) {
        if (threadIdx.x < s) s_red[threadIdx.x] += s_red[threadIdx.x + s];
        __syncthreads();
    }
    if (threadIdx.x == 0) out[0] = s_red[0] * (1.0f / (float)BATCH);
}

extern "C" void kernel_launch(void* const* d_in, const int* in_sizes, int n_in,
                              void* d_out, int out_size)
{
    const float* src = (const float*)d_in[0];   // [B, N, 3]
    const float* tgt = (const float*)d_in[1];   // [B, M, 3]
    const float* w   = (const float*)d_in[2];   // [B, N]
    float* out = (float*)d_out;

    // 2 dirs * 4 batches * 16 point-groups * 16 splits = 2048 blocks
    chamfer_pass1<<<2 * BATCH * (NPTS / PPB) * SPLITS, T1>>>(src, tgt);
    chamfer_pass2<<<256, 256>>>(w);
    chamfer_pass3<<<1, 256>>>(out);
}